// round 1
// baseline (speedup 1.0000x reference)
#include <cuda_runtime.h>
#include <math.h>

#define NN   20000
#define EE   320000
#define FIN  256
#define H1   512
#define NHEAD 8
#define NCLS 64
#define NEG  0.2f
#define EPSI 1e-16f

// ---------------- scratch (static device globals; no allocation) ----------------
__device__ float g_xl1[NN * H1];
__device__ float g_xr1[NN * H1];
__device__ float g_h  [NN * H1];
__device__ float g_alpha1[EE * NHEAD];   // alpha, then ex (in place)
__device__ float g_inv1[NN * NHEAD];     // 1/(denom+eps)
__device__ float g_xl2[NN * NCLS];
__device__ float g_xr2[NN * NCLS];
__device__ float g_alpha2[EE];           // alpha2, then ex2 (in place)
__device__ float g_inv2[NN];
__device__ int   g_deg[NN];
__device__ int   g_off[NN];
__device__ int   g_cur[NN];
__device__ int   g_elist[EE];

// ---------------- CSR build ----------------
__global__ void k_zero_deg() {
    int i = blockIdx.x * blockDim.x + threadIdx.x;
    if (i < NN) g_deg[i] = 0;
}

__global__ void k_hist(const int* __restrict__ dst) {
    int e = blockIdx.x * blockDim.x + threadIdx.x;
    if (e < EE) atomicAdd(&g_deg[dst[e]], 1);
}

// single-block exclusive scan of deg -> off (and cursor copy)
__global__ void k_scan() {
    const int PER = 20;                      // 1024*20 = 20480 >= NN
    __shared__ int wsum[32];
    int tid  = threadIdx.x;
    int base = tid * PER;
    int loc[PER];
    int s = 0;
#pragma unroll
    for (int i = 0; i < PER; i++) {
        int v = (base + i < NN) ? g_deg[base + i] : 0;
        loc[i] = s; s += v;
    }
    int lane = tid & 31, w = tid >> 5;
    int x = s;
#pragma unroll
    for (int o = 1; o < 32; o <<= 1) {
        int y = __shfl_up_sync(0xffffffffu, x, o);
        if (lane >= o) x += y;
    }
    if (lane == 31) wsum[w] = x;
    __syncthreads();
    if (w == 0) {
        int v = wsum[lane];
#pragma unroll
        for (int o = 1; o < 32; o <<= 1) {
            int y = __shfl_up_sync(0xffffffffu, v, o);
            if (lane >= o) v += y;
        }
        wsum[lane] = v;
    }
    __syncthreads();
    int pre = x - s + (w > 0 ? wsum[w - 1] : 0);
#pragma unroll
    for (int i = 0; i < PER; i++) {
        if (base + i < NN) {
            int o = pre + loc[i];
            g_off[base + i] = o;
            g_cur[base + i] = o;
        }
    }
}

__global__ void k_scatter(const int* __restrict__ dst) {
    int e = blockIdx.x * blockDim.x + threadIdx.x;
    if (e < EE) {
        int p = atomicAdd(&g_cur[dst[e]], 1);
        g_elist[p] = e;
    }
}

// ---------------- SIMT fp32 GEMM, C[M,Nn] = A[M,K] @ B[K,Nn] ----------------
// Nn % BN == 0 and K % BK == 0 assumed (holds for all 4 GEMMs). M guarded.
template <int BM, int BN, int BK, int TM, int TN>
__global__ __launch_bounds__(256)
void gemm_k(const float* __restrict__ A, const float* __restrict__ B,
            float* __restrict__ C, int M, int Nn, int K) {
    __shared__ float As[BK][BM];
    __shared__ float Bs[BK][BN];
    const int tid = threadIdx.x;                 // 256
    const int tx = tid % (BN / TN);
    const int ty = tid / (BN / TN);
    const int row0 = blockIdx.y * BM, col0 = blockIdx.x * BN;
    float acc[TM][TN];
#pragma unroll
    for (int i = 0; i < TM; i++)
#pragma unroll
        for (int j = 0; j < TN; j++) acc[i][j] = 0.f;

    const int ACNT = BM * BK / (4 * 256);
    const int BCNT = BK * BN / (4 * 256);

    for (int k0 = 0; k0 < K; k0 += BK) {
#pragma unroll
        for (int t = 0; t < ACNT; t++) {
            int idx = tid + t * 256;
            int kq = idx % (BK / 4);
            int m  = idx / (BK / 4);
            float4 av = make_float4(0.f, 0.f, 0.f, 0.f);
            if (row0 + m < M)
                av = *(const float4*)(A + (long)(row0 + m) * K + k0 + kq * 4);
            As[kq * 4 + 0][m] = av.x;
            As[kq * 4 + 1][m] = av.y;
            As[kq * 4 + 2][m] = av.z;
            As[kq * 4 + 3][m] = av.w;
        }
#pragma unroll
        for (int t = 0; t < BCNT; t++) {
            int idx = tid + t * 256;
            int nq = idx % (BN / 4);
            int kk = idx / (BN / 4);
            *(float4*)&Bs[kk][nq * 4] =
                *(const float4*)(B + (long)(k0 + kk) * Nn + col0 + nq * 4);
        }
        __syncthreads();
#pragma unroll
        for (int k = 0; k < BK; k++) {
            float a[TM], b[TN];
#pragma unroll
            for (int i = 0; i < TM; i += 4)
                *(float4*)&a[i] = *(float4*)&As[k][ty * TM + i];
#pragma unroll
            for (int j = 0; j < TN; j += 4)
                *(float4*)&b[j] = *(float4*)&Bs[k][tx * TN + j];
#pragma unroll
            for (int i = 0; i < TM; i++)
#pragma unroll
                for (int j = 0; j < TN; j++) acc[i][j] += a[i] * b[j];
        }
        __syncthreads();
    }
#pragma unroll
    for (int i = 0; i < TM; i++) {
        int r = row0 + ty * TM + i;
        if (r < M) {
#pragma unroll
            for (int j = 0; j < TN; j += 4)
                *(float4*)(C + (long)r * Nn + col0 + tx * TN + j) = *(float4*)&acc[i][j];
        }
    }
}

// ---------------- layer-1 edge kernels ----------------
// per-edge alpha via warp-per-dst-node (xr kept in registers)
__global__ void k_score1(const int* __restrict__ src, const float* __restrict__ att1) {
    int gw   = (blockIdx.x * blockDim.x + threadIdx.x) >> 5;
    int lane = threadIdx.x & 31;
    if (gw >= NN) return;
    int d = g_deg[gw];
    if (d == 0) return;
    int start = g_off[gw];
    const float4* xlv = (const float4*)g_xl1;
    const float4* xrv = (const float4*)g_xr1;
    const float4* atv = (const float4*)att1;
    float4 xr[4], at[4];
#pragma unroll
    for (int j = 0; j < 4; j++) {
        xr[j] = xrv[gw * 128 + lane * 4 + j];
        at[j] = atv[lane * 4 + j];
    }
    int e = g_elist[start];
    int s = src[e];
    for (int i = 0; i < d; i++) {
        int e2 = 0, s2 = 0;
        if (i + 1 < d) { e2 = g_elist[start + i + 1]; s2 = src[e2]; }
        float sum = 0.f;
#pragma unroll
        for (int j = 0; j < 4; j++) {
            float4 a = xlv[s * 128 + lane * 4 + j];
            float t;
            t = a.x + xr[j].x; t = t > 0.f ? t : NEG * t; sum += t * at[j].x;
            t = a.y + xr[j].y; t = t > 0.f ? t : NEG * t; sum += t * at[j].y;
            t = a.z + xr[j].z; t = t > 0.f ? t : NEG * t; sum += t * at[j].z;
            t = a.w + xr[j].w; t = t > 0.f ? t : NEG * t; sum += t * at[j].w;
        }
        sum += __shfl_xor_sync(0xffffffffu, sum, 1);
        sum += __shfl_xor_sync(0xffffffffu, sum, 2);
        if ((lane & 3) == 0) g_alpha1[e * 8 + (lane >> 2)] = sum;
        e = e2; s = s2;
    }
}

// per-node softmax: max, exp (stored in place), 1/(sum+eps)
__global__ void k_w1() {
    int gw   = (blockIdx.x * blockDim.x + threadIdx.x) >> 5;
    int lane = threadIdx.x & 31;
    if (gw >= NN) return;
    int d = g_deg[gw];
    if (d == 0) return;
    int start = g_off[gw];
    const float4* aL = (const float4*)g_alpha1;
    float4*       aS = (float4*)g_alpha1;
    float mx[8];
#pragma unroll
    for (int h = 0; h < 8; h++) mx[h] = -3.402823466e38f;
    for (int i = lane; i < d; i += 32) {
        int e = g_elist[start + i];
        float4 a = aL[e * 2], b = aL[e * 2 + 1];
        mx[0] = fmaxf(mx[0], a.x); mx[1] = fmaxf(mx[1], a.y);
        mx[2] = fmaxf(mx[2], a.z); mx[3] = fmaxf(mx[3], a.w);
        mx[4] = fmaxf(mx[4], b.x); mx[5] = fmaxf(mx[5], b.y);
        mx[6] = fmaxf(mx[6], b.z); mx[7] = fmaxf(mx[7], b.w);
    }
#pragma unroll
    for (int h = 0; h < 8; h++)
#pragma unroll
        for (int o = 16; o; o >>= 1)
            mx[h] = fmaxf(mx[h], __shfl_xor_sync(0xffffffffu, mx[h], o));
    float sm[8];
#pragma unroll
    for (int h = 0; h < 8; h++) sm[h] = 0.f;
    for (int i = lane; i < d; i += 32) {
        int e = g_elist[start + i];
        float4 a = aL[e * 2], b = aL[e * 2 + 1];
        a.x = expf(a.x - mx[0]); a.y = expf(a.y - mx[1]);
        a.z = expf(a.z - mx[2]); a.w = expf(a.w - mx[3]);
        b.x = expf(b.x - mx[4]); b.y = expf(b.y - mx[5]);
        b.z = expf(b.z - mx[6]); b.w = expf(b.w - mx[7]);
        sm[0] += a.x; sm[1] += a.y; sm[2] += a.z; sm[3] += a.w;
        sm[4] += b.x; sm[5] += b.y; sm[6] += b.z; sm[7] += b.w;
        aS[e * 2] = a; aS[e * 2 + 1] = b;
    }
#pragma unroll
    for (int h = 0; h < 8; h++)
#pragma unroll
        for (int o = 16; o; o >>= 1)
            sm[h] += __shfl_xor_sync(0xffffffffu, sm[h], o);
    if (lane == 0) {
#pragma unroll
        for (int h = 0; h < 8; h++) g_inv1[gw * 8 + h] = 1.f / (sm[h] + EPSI);
    }
}

// gather-aggregate + bias + elu, one 128-thread block per node (no atomics)
__global__ void k_aggr1(const int* __restrict__ src, const float* __restrict__ b1) {
    int n   = blockIdx.x;
    int tid = threadIdx.x;           // 128: tid*4 channels, head = tid/16
    int d = g_deg[n], start = g_off[n];
    int h = tid >> 4;
    __shared__ float inv_s[8];
    if (tid < 8) inv_s[tid] = g_inv1[n * 8 + tid];
    __syncthreads();
    float inv = inv_s[h];
    const float4* xlv = (const float4*)g_xl1;
    float4 acc = make_float4(0.f, 0.f, 0.f, 0.f);
    int e = 0, s = 0;
    if (d > 0) { e = g_elist[start]; s = src[e]; }
    for (int i = 0; i < d; i++) {
        int e2 = 0, s2 = 0;
        if (i + 1 < d) { e2 = g_elist[start + i + 1]; s2 = src[e2]; }
        float w  = g_alpha1[e * 8 + h] * inv;
        float4 v = xlv[s * 128 + tid];
        acc.x += w * v.x; acc.y += w * v.y; acc.z += w * v.z; acc.w += w * v.w;
        e = e2; s = s2;
    }
    int c0 = tid * 4;
    float4 bb = *(const float4*)(b1 + c0);
    float4 o;
    o.x = acc.x + bb.x; o.x = o.x > 0.f ? o.x : expm1f(o.x);
    o.y = acc.y + bb.y; o.y = o.y > 0.f ? o.y : expm1f(o.y);
    o.z = acc.z + bb.z; o.z = o.z > 0.f ? o.z : expm1f(o.z);
    o.w = acc.w + bb.w; o.w = o.w > 0.f ? o.w : expm1f(o.w);
    ((float4*)g_h)[n * 128 + tid] = o;
}

// ---------------- layer-2 edge kernels (heads = 1, C = 64) ----------------
__global__ void k_score2(const int* __restrict__ src, const float* __restrict__ att2) {
    int gw   = (blockIdx.x * blockDim.x + threadIdx.x) >> 5;
    int lane = threadIdx.x & 31;
    if (gw >= NN) return;
    int d = g_deg[gw];
    if (d == 0) return;
    int start = g_off[gw];
    const float2* xlv = (const float2*)g_xl2;
    const float2* xrv = (const float2*)g_xr2;
    float2 xr = xrv[gw * 32 + lane];
    float2 at = ((const float2*)att2)[lane];
    int e = g_elist[start];
    int s = src[e];
    for (int i = 0; i < d; i++) {
        int e2 = 0, s2 = 0;
        if (i + 1 < d) { e2 = g_elist[start + i + 1]; s2 = src[e2]; }
        float2 a = xlv[s * 32 + lane];
        float t0 = a.x + xr.x; t0 = t0 > 0.f ? t0 : NEG * t0;
        float t1 = a.y + xr.y; t1 = t1 > 0.f ? t1 : NEG * t1;
        float sum = t0 * at.x + t1 * at.y;
#pragma unroll
        for (int o = 16; o; o >>= 1) sum += __shfl_xor_sync(0xffffffffu, sum, o);
        if (lane == 0) g_alpha2[e] = sum;
        e = e2; s = s2;
    }
}

__global__ void k_w2() {
    int gw   = (blockIdx.x * blockDim.x + threadIdx.x) >> 5;
    int lane = threadIdx.x & 31;
    if (gw >= NN) return;
    int d = g_deg[gw];
    if (d == 0) return;
    int start = g_off[gw];
    float mx = -3.402823466e38f;
    for (int i = lane; i < d; i += 32) mx = fmaxf(mx, g_alpha2[g_elist[start + i]]);
#pragma unroll
    for (int o = 16; o; o >>= 1) mx = fmaxf(mx, __shfl_xor_sync(0xffffffffu, mx, o));
    float sm = 0.f;
    for (int i = lane; i < d; i += 32) {
        int e = g_elist[start + i];
        float ex = expf(g_alpha2[e] - mx);
        g_alpha2[e] = ex;
        sm += ex;
    }
#pragma unroll
    for (int o = 16; o; o >>= 1) sm += __shfl_xor_sync(0xffffffffu, sm, o);
    if (lane == 0) g_inv2[gw] = 1.f / (sm + EPSI);
}

__global__ void k_aggr2(const int* __restrict__ src, const float* __restrict__ b2,
                        float* __restrict__ out) {
    int n   = blockIdx.x;
    int tid = threadIdx.x;            // 64, one channel each
    int d = g_deg[n], start = g_off[n];
    float inv = g_inv2[n];
    float acc = 0.f;
    int e = 0, s = 0;
    if (d > 0) { e = g_elist[start]; s = src[e]; }
    for (int i = 0; i < d; i++) {
        int e2 = 0, s2 = 0;
        if (i + 1 < d) { e2 = g_elist[start + i + 1]; s2 = src[e2]; }
        float w = g_alpha2[e] * inv;
        acc += w * g_xl2[s * 64 + tid];
        e = e2; s = s2;
    }
    out[n * 64 + tid] = acc + b2[tid];
}

// ---------------- launch ----------------
extern "C" void kernel_launch(void* const* d_in, const int* in_sizes, int n_in,
                              void* d_out, int out_size) {
    const float* x    = (const float*)d_in[0];
    const int*   ei   = (const int*)d_in[1];
    const float* Wl1  = (const float*)d_in[2];
    const float* Wr1  = (const float*)d_in[3];
    const float* att1 = (const float*)d_in[4];
    const float* b1   = (const float*)d_in[5];
    const float* Wl2  = (const float*)d_in[6];
    const float* Wr2  = (const float*)d_in[7];
    const float* att2 = (const float*)d_in[8];
    const float* b2   = (const float*)d_in[9];
    float* out = (float*)d_out;
    const int* srcA = ei;
    const int* dstA = ei + EE;

    float *xl1, *xr1, *hb, *xl2, *xr2;
    cudaGetSymbolAddress((void**)&xl1, g_xl1);
    cudaGetSymbolAddress((void**)&xr1, g_xr1);
    cudaGetSymbolAddress((void**)&hb,  g_h);
    cudaGetSymbolAddress((void**)&xl2, g_xl2);
    cudaGetSymbolAddress((void**)&xr2, g_xr2);

    // CSR by destination
    k_zero_deg<<<(NN + 255) / 256, 256>>>();
    k_hist<<<(EE + 255) / 256, 256>>>(dstA);
    k_scan<<<1, 1024>>>();
    k_scatter<<<(EE + 255) / 256, 256>>>(dstA);

    // layer-1 projections
    gemm_k<128, 128, 8, 8, 8><<<dim3(H1 / 128, (NN + 127) / 128), 256>>>(x, Wl1, xl1, NN, H1, FIN);
    gemm_k<128, 128, 8, 8, 8><<<dim3(H1 / 128, (NN + 127) / 128), 256>>>(x, Wr1, xr1, NN, H1, FIN);

    // layer-1 attention + aggregate
    k_score1<<<(NN * 32 + 255) / 256, 256>>>(srcA, att1);
    k_w1<<<(NN * 32 + 255) / 256, 256>>>();
    k_aggr1<<<NN, 128>>>(srcA, b1);

    // layer-2 projections
    gemm_k<128, 64, 16, 8, 4><<<dim3(NCLS / 64, (NN + 127) / 128), 256>>>(hb, Wl2, xl2, NN, NCLS, H1);
    gemm_k<128, 64, 16, 8, 4><<<dim3(NCLS / 64, (NN + 127) / 128), 256>>>(hb, Wr2, xr2, NN, NCLS, H1);

    // layer-2 attention + aggregate (writes every output element)
    k_score2<<<(NN * 32 + 255) / 256, 256>>>(srcA, att2);
    k_w2<<<(NN * 32 + 255) / 256, 256>>>();
    k_aggr2<<<NN, 64>>>(srcA, b2, out);
}

// round 3
// speedup vs baseline: 1.6348x; 1.6348x over previous
#include <cuda_runtime.h>
#include <math.h>
#include <stdint.h>

#define NN   20000
#define EE   320000
#define FIN  256
#define H1   512
#define NHEAD 8
#define NCLS 64
#define NEG  0.2f
#define EPSI 1e-16f

// ---------------- scratch (static device globals; no allocation) ----------------
__device__ float g_xl1[NN * H1];
__device__ float g_xr1[NN * H1];
__device__ float g_h  [NN * H1];
__device__ float g_alpha1[EE * NHEAD];
__device__ float g_inv1[NN * NHEAD];
__device__ float g_xl2[NN * NCLS];
__device__ float g_xr2[NN * NCLS];
__device__ float g_alpha2[EE];
__device__ float g_inv2[NN];
__device__ int   g_deg[NN];
__device__ int   g_off[NN];
__device__ int   g_cur[NN];
__device__ int   g_elist[EE];
// transposed weights (K-major for B operand of mma: Bt[n][k])
__device__ float g_wt1l[H1 * FIN];
__device__ float g_wt1r[H1 * FIN];
__device__ float g_wt2l[NCLS * H1];
__device__ float g_wt2r[NCLS * H1];

// ---------------- tf32 helpers ----------------
__device__ __forceinline__ uint32_t f2tf32(float f) {
    uint32_t u;
    asm("cvt.rna.tf32.f32 %0, %1;" : "=r"(u) : "f"(f));
    return u;
}

__device__ __forceinline__ void mma_tf32(float c[4], uint32_t a0, uint32_t a1,
                                         uint32_t a2, uint32_t a3,
                                         uint32_t b0, uint32_t b1) {
    asm volatile(
        "mma.sync.aligned.m16n8k8.row.col.f32.tf32.tf32.f32 "
        "{%0,%1,%2,%3}, {%4,%5,%6,%7}, {%8,%9}, {%0,%1,%2,%3};"
        : "+f"(c[0]), "+f"(c[1]), "+f"(c[2]), "+f"(c[3])
        : "r"(a0), "r"(a1), "r"(a2), "r"(a3), "r"(b0), "r"(b1));
}

// ---------------- tensor-core GEMM: C[M,Nn] = A[M,K] @ Bt[Nn,K]^T ----------------
// BM=128, BN=64, BK=32. 8 warps in 4(m) x 2(n); warp tile 32x32 via m16n8k8.
// Requires Nn % 64 == 0, K % 32 == 0. M guarded.
#define PAD 36

__global__ __launch_bounds__(256, 2)
void gemm_mma(const float* __restrict__ A, const float* __restrict__ Bt,
              float* __restrict__ C, int M, int Nn, int K) {
    __shared__ uint32_t As[128 * PAD];
    __shared__ uint32_t Bs[64 * PAD];
    const int tid = threadIdx.x, wid = tid >> 5, lane = tid & 31;
    const int warpM = wid & 3, warpN = wid >> 2;
    const int row0 = blockIdx.y * 128, col0 = blockIdx.x * 64;
    const int gr = lane >> 2, gc = lane & 3;

    float c[2][4][4];
#pragma unroll
    for (int i = 0; i < 2; i++)
#pragma unroll
        for (int j = 0; j < 4; j++)
#pragma unroll
            for (int t = 0; t < 4; t++) c[i][j][t] = 0.f;

    for (int k0 = 0; k0 < K; k0 += 32) {
        // stage A: 128 x 32 floats (1024 float4, 4 per thread), cvt to tf32
#pragma unroll
        for (int t = 0; t < 4; t++) {
            int idx = tid + t * 256;
            int r = idx >> 3, cq = idx & 7;
            float4 v = make_float4(0.f, 0.f, 0.f, 0.f);
            if (row0 + r < M)
                v = *(const float4*)(A + (size_t)(row0 + r) * K + k0 + cq * 4);
            uint32_t* p = As + r * PAD + cq * 4;
            p[0] = f2tf32(v.x); p[1] = f2tf32(v.y);
            p[2] = f2tf32(v.z); p[3] = f2tf32(v.w);
        }
        // stage B: 64 x 32 floats (512 float4, 2 per thread)
#pragma unroll
        for (int t = 0; t < 2; t++) {
            int idx = tid + t * 256;
            int r = idx >> 3, cq = idx & 7;
            float4 v = *(const float4*)(Bt + (size_t)(col0 + r) * K + k0 + cq * 4);
            uint32_t* p = Bs + r * PAD + cq * 4;
            p[0] = f2tf32(v.x); p[1] = f2tf32(v.y);
            p[2] = f2tf32(v.z); p[3] = f2tf32(v.w);
        }
        __syncthreads();
#pragma unroll
        for (int ks = 0; ks < 4; ks++) {
            uint32_t a[2][4], b[4][2];
#pragma unroll
            for (int i = 0; i < 2; i++) {
                const uint32_t* ap = As + (warpM * 32 + i * 16 + gr) * PAD + ks * 8 + gc;
                a[i][0] = ap[0];
                a[i][1] = ap[8 * PAD];
                a[i][2] = ap[4];
                a[i][3] = ap[8 * PAD + 4];
            }
#pragma unroll
            for (int j = 0; j < 4; j++) {
                const uint32_t* bp = Bs + (warpN * 32 + j * 8 + gr) * PAD + ks * 8 + gc;
                b[j][0] = bp[0];
                b[j][1] = bp[4];
            }
#pragma unroll
            for (int i = 0; i < 2; i++)
#pragma unroll
                for (int j = 0; j < 4; j++)
                    mma_tf32(c[i][j], a[i][0], a[i][1], a[i][2], a[i][3],
                             b[j][0], b[j][1]);
        }
        __syncthreads();
    }
    // epilogue
#pragma unroll
    for (int i = 0; i < 2; i++) {
        int r = row0 + warpM * 32 + i * 16 + gr;
#pragma unroll
        for (int j = 0; j < 4; j++) {
            int cc = col0 + warpN * 32 + j * 8 + 2 * gc;
            if (r < M)
                *(float2*)(C + (size_t)r * Nn + cc) = make_float2(c[i][j][0], c[i][j][1]);
            if (r + 8 < M)
                *(float2*)(C + (size_t)(r + 8) * Nn + cc) = make_float2(c[i][j][2], c[i][j][3]);
        }
    }
}

// ---------------- weight transpose: out[c][r] = in[r][c] ----------------
__global__ void k_transpose(const float* __restrict__ in, float* __restrict__ out,
                            int R, int C) {
    __shared__ float t[32][33];
    int bx = blockIdx.x * 32, by = blockIdx.y * 32;
    int x = bx + threadIdx.x;
#pragma unroll
    for (int j = 0; j < 32; j += 8) {
        int y = by + threadIdx.y + j;
        if (y < R && x < C) t[threadIdx.y + j][threadIdx.x] = in[(size_t)y * C + x];
    }
    __syncthreads();
    x = by + threadIdx.x;
#pragma unroll
    for (int j = 0; j < 32; j += 8) {
        int y = bx + threadIdx.y + j;
        if (y < C && x < R) out[(size_t)y * R + x] = t[threadIdx.x][threadIdx.y + j];
    }
}

// ---------------- CSR build ----------------
__global__ void k_zero_deg() {
    int i = blockIdx.x * blockDim.x + threadIdx.x;
    if (i < NN) g_deg[i] = 0;
}

__global__ void k_hist(const int* __restrict__ dst) {
    int e = blockIdx.x * blockDim.x + threadIdx.x;
    if (e < EE) atomicAdd(&g_deg[dst[e]], 1);
}

__global__ void k_scan() {
    const int PER = 20;
    __shared__ int wsum[32];
    int tid  = threadIdx.x;
    int base = tid * PER;
    int loc[PER];
    int s = 0;
#pragma unroll
    for (int i = 0; i < PER; i++) {
        int v = (base + i < NN) ? g_deg[base + i] : 0;
        loc[i] = s; s += v;
    }
    int lane = tid & 31, w = tid >> 5;
    int x = s;
#pragma unroll
    for (int o = 1; o < 32; o <<= 1) {
        int y = __shfl_up_sync(0xffffffffu, x, o);
        if (lane >= o) x += y;
    }
    if (lane == 31) wsum[w] = x;
    __syncthreads();
    if (w == 0) {
        int v = wsum[lane];
#pragma unroll
        for (int o = 1; o < 32; o <<= 1) {
            int y = __shfl_up_sync(0xffffffffu, v, o);
            if (lane >= o) v += y;
        }
        wsum[lane] = v;
    }
    __syncthreads();
    int pre = x - s + (w > 0 ? wsum[w - 1] : 0);
#pragma unroll
    for (int i = 0; i < PER; i++) {
        if (base + i < NN) {
            int o = pre + loc[i];
            g_off[base + i] = o;
            g_cur[base + i] = o;
        }
    }
}

__global__ void k_scatter(const int* __restrict__ dst) {
    int e = blockIdx.x * blockDim.x + threadIdx.x;
    if (e < EE) {
        int p = atomicAdd(&g_cur[dst[e]], 1);
        g_elist[p] = e;
    }
}

// ---------------- layer-1 edge kernels ----------------
__global__ void k_score1(const int* __restrict__ src, const float* __restrict__ att1) {
    int gw   = (blockIdx.x * blockDim.x + threadIdx.x) >> 5;
    int lane = threadIdx.x & 31;
    if (gw >= NN) return;
    int d = g_deg[gw];
    if (d == 0) return;
    int start = g_off[gw];
    const float4* xlv = (const float4*)g_xl1;
    const float4* xrv = (const float4*)g_xr1;
    const float4* atv = (const float4*)att1;
    float4 xr[4], at[4];
#pragma unroll
    for (int j = 0; j < 4; j++) {
        xr[j] = xrv[gw * 128 + lane * 4 + j];
        at[j] = atv[lane * 4 + j];
    }
    int e = g_elist[start];
    int s = src[e];
    for (int i = 0; i < d; i++) {
        int e2 = 0, s2 = 0;
        if (i + 1 < d) { e2 = g_elist[start + i + 1]; s2 = src[e2]; }
        float sum = 0.f;
#pragma unroll
        for (int j = 0; j < 4; j++) {
            float4 a = xlv[s * 128 + lane * 4 + j];
            float t;
            t = a.x + xr[j].x; t = t > 0.f ? t : NEG * t; sum += t * at[j].x;
            t = a.y + xr[j].y; t = t > 0.f ? t : NEG * t; sum += t * at[j].y;
            t = a.z + xr[j].z; t = t > 0.f ? t : NEG * t; sum += t * at[j].z;
            t = a.w + xr[j].w; t = t > 0.f ? t : NEG * t; sum += t * at[j].w;
        }
        sum += __shfl_xor_sync(0xffffffffu, sum, 1);
        sum += __shfl_xor_sync(0xffffffffu, sum, 2);
        if ((lane & 3) == 0) g_alpha1[e * 8 + (lane >> 2)] = sum;
        e = e2; s = s2;
    }
}

__global__ void k_w1() {
    int gw   = (blockIdx.x * blockDim.x + threadIdx.x) >> 5;
    int lane = threadIdx.x & 31;
    if (gw >= NN) return;
    int d = g_deg[gw];
    if (d == 0) return;
    int start = g_off[gw];
    const float4* aL = (const float4*)g_alpha1;
    float4*       aS = (float4*)g_alpha1;
    float mx[8];
#pragma unroll
    for (int h = 0; h < 8; h++) mx[h] = -3.402823466e38f;
    for (int i = lane; i < d; i += 32) {
        int e = g_elist[start + i];
        float4 a = aL[e * 2], b = aL[e * 2 + 1];
        mx[0] = fmaxf(mx[0], a.x); mx[1] = fmaxf(mx[1], a.y);
        mx[2] = fmaxf(mx[2], a.z); mx[3] = fmaxf(mx[3], a.w);
        mx[4] = fmaxf(mx[4], b.x); mx[5] = fmaxf(mx[5], b.y);
        mx[6] = fmaxf(mx[6], b.z); mx[7] = fmaxf(mx[7], b.w);
    }
#pragma unroll
    for (int h = 0; h < 8; h++)
#pragma unroll
        for (int o = 16; o; o >>= 1)
            mx[h] = fmaxf(mx[h], __shfl_xor_sync(0xffffffffu, mx[h], o));
    float sm[8];
#pragma unroll
    for (int h = 0; h < 8; h++) sm[h] = 0.f;
    for (int i = lane; i < d; i += 32) {
        int e = g_elist[start + i];
        float4 a = aL[e * 2], b = aL[e * 2 + 1];
        a.x = expf(a.x - mx[0]); a.y = expf(a.y - mx[1]);
        a.z = expf(a.z - mx[2]); a.w = expf(a.w - mx[3]);
        b.x = expf(b.x - mx[4]); b.y = expf(b.y - mx[5]);
        b.z = expf(b.z - mx[6]); b.w = expf(b.w - mx[7]);
        sm[0] += a.x; sm[1] += a.y; sm[2] += a.z; sm[3] += a.w;
        sm[4] += b.x; sm[5] += b.y; sm[6] += b.z; sm[7] += b.w;
        aS[e * 2] = a; aS[e * 2 + 1] = b;
    }
#pragma unroll
    for (int h = 0; h < 8; h++)
#pragma unroll
        for (int o = 16; o; o >>= 1)
            sm[h] += __shfl_xor_sync(0xffffffffu, sm[h], o);
    if (lane == 0) {
#pragma unroll
        for (int h = 0; h < 8; h++) g_inv1[gw * 8 + h] = 1.f / (sm[h] + EPSI);
    }
}

__global__ void k_aggr1(const int* __restrict__ src, const float* __restrict__ b1) {
    int n   = blockIdx.x;
    int tid = threadIdx.x;
    int d = g_deg[n], start = g_off[n];
    int h = tid >> 4;
    __shared__ float inv_s[8];
    if (tid < 8) inv_s[tid] = g_inv1[n * 8 + tid];
    __syncthreads();
    float inv = inv_s[h];
    const float4* xlv = (const float4*)g_xl1;
    float4 acc = make_float4(0.f, 0.f, 0.f, 0.f);
    int e = 0, s = 0;
    if (d > 0) { e = g_elist[start]; s = src[e]; }
    for (int i = 0; i < d; i++) {
        int e2 = 0, s2 = 0;
        if (i + 1 < d) { e2 = g_elist[start + i + 1]; s2 = src[e2]; }
        float w  = g_alpha1[e * 8 + h] * inv;
        float4 v = xlv[s * 128 + tid];
        acc.x += w * v.x; acc.y += w * v.y; acc.z += w * v.z; acc.w += w * v.w;
        e = e2; s = s2;
    }
    int c0 = tid * 4;
    float4 bb = *(const float4*)(b1 + c0);
    float4 o;
    o.x = acc.x + bb.x; o.x = o.x > 0.f ? o.x : expm1f(o.x);
    o.y = acc.y + bb.y; o.y = o.y > 0.f ? o.y : expm1f(o.y);
    o.z = acc.z + bb.z; o.z = o.z > 0.f ? o.z : expm1f(o.z);
    o.w = acc.w + bb.w; o.w = o.w > 0.f ? o.w : expm1f(o.w);
    ((float4*)g_h)[n * 128 + tid] = o;
}

// ---------------- layer-2 edge kernels ----------------
__global__ void k_score2(const int* __restrict__ src, const float* __restrict__ att2) {
    int gw   = (blockIdx.x * blockDim.x + threadIdx.x) >> 5;
    int lane = threadIdx.x & 31;
    if (gw >= NN) return;
    int d = g_deg[gw];
    if (d == 0) return;
    int start = g_off[gw];
    const float2* xlv = (const float2*)g_xl2;
    const float2* xrv = (const float2*)g_xr2;
    float2 xr = xrv[gw * 32 + lane];
    float2 at = ((const float2*)att2)[lane];
    int e = g_elist[start];
    int s = src[e];
    for (int i = 0; i < d; i++) {
        int e2 = 0, s2 = 0;
        if (i + 1 < d) { e2 = g_elist[start + i + 1]; s2 = src[e2]; }
        float2 a = xlv[s * 32 + lane];
        float t0 = a.x + xr.x; t0 = t0 > 0.f ? t0 : NEG * t0;
        float t1 = a.y + xr.y; t1 = t1 > 0.f ? t1 : NEG * t1;
        float sum = t0 * at.x + t1 * at.y;
#pragma unroll
        for (int o = 16; o; o >>= 1) sum += __shfl_xor_sync(0xffffffffu, sum, o);
        if (lane == 0) g_alpha2[e] = sum;
        e = e2; s = s2;
    }
}

__global__ void k_w2() {
    int gw   = (blockIdx.x * blockDim.x + threadIdx.x) >> 5;
    int lane = threadIdx.x & 31;
    if (gw >= NN) return;
    int d = g_deg[gw];
    if (d == 0) return;
    int start = g_off[gw];
    float mx = -3.402823466e38f;
    for (int i = lane; i < d; i += 32) mx = fmaxf(mx, g_alpha2[g_elist[start + i]]);
#pragma unroll
    for (int o = 16; o; o >>= 1) mx = fmaxf(mx, __shfl_xor_sync(0xffffffffu, mx, o));
    float sm = 0.f;
    for (int i = lane; i < d; i += 32) {
        int e = g_elist[start + i];
        float ex = expf(g_alpha2[e] - mx);
        g_alpha2[e] = ex;
        sm += ex;
    }
#pragma unroll
    for (int o = 16; o; o >>= 1) sm += __shfl_xor_sync(0xffffffffu, sm, o);
    if (lane == 0) g_inv2[gw] = 1.f / (sm + EPSI);
}

__global__ void k_aggr2(const int* __restrict__ src, const float* __restrict__ b2,
                        float* __restrict__ out) {
    int n   = blockIdx.x;
    int tid = threadIdx.x;
    int d = g_deg[n], start = g_off[n];
    float inv = g_inv2[n];
    float acc = 0.f;
    int e = 0, s = 0;
    if (d > 0) { e = g_elist[start]; s = src[e]; }
    for (int i = 0; i < d; i++) {
        int e2 = 0, s2 = 0;
        if (i + 1 < d) { e2 = g_elist[start + i + 1]; s2 = src[e2]; }
        float w = g_alpha2[e] * inv;
        acc += w * g_xl2[s * 64 + tid];
        e = e2; s = s2;
    }
    out[n * 64 + tid] = acc + b2[tid];
}

// ---------------- launch ----------------
extern "C" void kernel_launch(void* const* d_in, const int* in_sizes, int n_in,
                              void* d_out, int out_size) {
    const float* x    = (const float*)d_in[0];
    const int*   ei   = (const int*)d_in[1];
    const float* Wl1  = (const float*)d_in[2];
    const float* Wr1  = (const float*)d_in[3];
    const float* att1 = (const float*)d_in[4];
    const float* b1   = (const float*)d_in[5];
    const float* Wl2  = (const float*)d_in[6];
    const float* Wr2  = (const float*)d_in[7];
    const float* att2 = (const float*)d_in[8];
    const float* b2   = (const float*)d_in[9];
    float* out = (float*)d_out;
    const int* srcA = ei;
    const int* dstA = ei + EE;

    float *xl1, *xr1, *hb, *xl2, *xr2, *wt1l, *wt1r, *wt2l, *wt2r;
    cudaGetSymbolAddress((void**)&xl1, g_xl1);
    cudaGetSymbolAddress((void**)&xr1, g_xr1);
    cudaGetSymbolAddress((void**)&hb,  g_h);
    cudaGetSymbolAddress((void**)&xl2, g_xl2);
    cudaGetSymbolAddress((void**)&xr2, g_xr2);
    cudaGetSymbolAddress((void**)&wt1l, g_wt1l);
    cudaGetSymbolAddress((void**)&wt1r, g_wt1r);
    cudaGetSymbolAddress((void**)&wt2l, g_wt2l);
    cudaGetSymbolAddress((void**)&wt2r, g_wt2r);

    // CSR by destination
    k_zero_deg<<<(NN + 255) / 256, 256>>>();
    k_hist<<<(EE + 255) / 256, 256>>>(dstA);
    k_scan<<<1, 1024>>>();
    k_scatter<<<(EE + 255) / 256, 256>>>(dstA);

    // weight transposes (K-major B operands)
    dim3 tb(32, 8);
    k_transpose<<<dim3(H1 / 32, FIN / 32), tb>>>(Wl1, wt1l, FIN, H1);
    k_transpose<<<dim3(H1 / 32, FIN / 32), tb>>>(Wr1, wt1r, FIN, H1);
    k_transpose<<<dim3(NCLS / 32, H1 / 32), tb>>>(Wl2, wt2l, H1, NCLS);
    k_transpose<<<dim3(NCLS / 32, H1 / 32), tb>>>(Wr2, wt2r, H1, NCLS);

    // layer-1 projections (mma.sync tf32)
    dim3 g1(H1 / 64, (NN + 127) / 128);
    gemm_mma<<<g1, 256>>>(x, wt1l, xl1, NN, H1, FIN);
    gemm_mma<<<g1, 256>>>(x, wt1r, xr1, NN, H1, FIN);

    // layer-1 attention + aggregate
    k_score1<<<(NN * 32 + 255) / 256, 256>>>(srcA, att1);
    k_w1<<<(NN * 32 + 255) / 256, 256>>>();
    k_aggr1<<<NN, 128>>>(srcA, b1);

    // layer-2 projections (mma.sync tf32)
    dim3 g2(NCLS / 64, (NN + 127) / 128);
    gemm_mma<<<g2, 256>>>(hb, wt2l, xl2, NN, NCLS, H1);
    gemm_mma<<<g2, 256>>>(hb, wt2r, xr2, NN, NCLS, H1);

    // layer-2 attention + aggregate
    k_score2<<<(NN * 32 + 255) / 256, 256>>>(srcA, att2);
    k_w2<<<(NN * 32 + 255) / 256, 256>>>();
    k_aggr2<<<NN, 64>>>(srcA, b2, out);
}